// round 1
// baseline (speedup 1.0000x reference)
#include <cuda_runtime.h>
#include <math_constants.h>

#define BB 4
#define NN 512
#define HH 8
#define FF 16
#define DH 128
#define TJ 16
#define TM 16

// ---- scratch (device globals: no allocation allowed) ----
__device__ float    d_h[2][BB*NN*DH];       // ping-pong hidden state
__device__ float    d_gl[BB*NN*DH];
__device__ float    d_gr[BB*NN*DH];
__device__ float    d_dl[BB*NN*HH];         // 0.6 * (a . g_l[n,h,:])
__device__ float    d_dr[BB*NN*HH];         // 0.6 * (a . g_r[n,h,:])
__device__ unsigned d_adjbits[BB*NN*(NN/32)];

// ---- pack adjacency rows into bitmasks (bit j of word j/32) ----
__global__ void pack_adj_kernel(const int* __restrict__ adj)
{
    int gw   = (blockIdx.x * blockDim.x + threadIdx.x) >> 5;   // row index b*N+i
    int lane = threadIdx.x & 31;
    if (gw >= BB*NN) return;
    const int* row = adj + gw * NN;
    #pragma unroll
    for (int w = 0; w < NN/32; w++) {
        unsigned bits = __ballot_sync(0xffffffffu, row[w*32 + lane] != 0);
        if (lane == 0) d_adjbits[gw*(NN/32) + w] = bits;
    }
}

// ---- h0 = X @ W_in  (Din = 2) ----
__global__ void in_proj_kernel(const float* __restrict__ x, const float* __restrict__ Win)
{
    int idx = blockIdx.x * blockDim.x + threadIdx.x;   // B*N*128 threads
    int n = idx >> 7, d = idx & 127;
    d_h[0][idx] = fmaf(x[n*2], Win[d], x[n*2+1] * Win[DH + d]);
}

// ---- per-layer projections: g_l = h@Wl, g_r = h@Wr, plus 0.6*(a.g) dots ----
__global__ void proj_kernel(const float* __restrict__ Wl, const float* __restrict__ Wr,
                            const float* __restrict__ a, int src)
{
    __shared__ __align__(16) float sh[TM][DH];
    const float* h = d_h[src];
    int n0 = blockIdx.x * TM;
    int t  = threadIdx.x;                       // 0..255
    for (int idx = t; idx < TM*DH; idx += 256)
        sh[idx >> 7][idx & 127] = h[n0*DH + idx];
    __syncthreads();

    int d = t & 127;
    const float* W   = (t < 128) ? Wl   : Wr;
    float*       g   = (t < 128) ? d_gl : d_gr;
    float*       dot = (t < 128) ? d_dl : d_dr;

    float acc[TM];
    #pragma unroll
    for (int m = 0; m < TM; m++) acc[m] = 0.f;

    for (int k = 0; k < DH; k += 4) {
        float w0 = W[(k+0)*DH + d];
        float w1 = W[(k+1)*DH + d];
        float w2 = W[(k+2)*DH + d];
        float w3 = W[(k+3)*DH + d];
        #pragma unroll
        for (int m = 0; m < TM; m++) {
            float4 hv = *(const float4*)&sh[m][k];
            acc[m] = fmaf(hv.x, w0, acc[m]);
            acc[m] = fmaf(hv.y, w1, acc[m]);
            acc[m] = fmaf(hv.z, w2, acc[m]);
            acc[m] = fmaf(hv.w, w3, acc[m]);
        }
    }

    float av = 0.6f * a[d & 15];
    #pragma unroll
    for (int m = 0; m < TM; m++) {
        g[(n0+m)*DH + d] = acc[m];
        float p = av * acc[m];
        p += __shfl_down_sync(0xffffffffu, p, 8, 16);
        p += __shfl_down_sync(0xffffffffu, p, 4, 16);
        p += __shfl_down_sync(0xffffffffu, p, 2, 16);
        p += __shfl_down_sync(0xffffffffu, p, 1, 16);
        if ((d & 15) == 0) dot[(n0+m)*HH + (d >> 4)] = p;
    }
}

// ---- fused GATv2 attention layer ----
// grid = B*H*(N/32) blocks, 128 threads (4 warps).
// lane = query row i within its 32-row tile; each warp owns a 128-wide j quarter.
// lrelu(t) = 0.6 t + 0.4|t|  =>  e = 0.6(a.gr_i) + 0.6(a.gl_j) + sum_f (0.4 a_f)|t_f|
__global__ void __launch_bounds__(128, 4) attn_kernel(const float* __restrict__ a, int src)
{
    __shared__ __align__(16) float s_gl[4][TJ][FF];
    __shared__ __align__(16) float s_gr[4][TJ][FF];
    __shared__ float s_dl[4][TJ];
    __shared__ float s_m[4][32];
    __shared__ float s_l[4][32];
    __shared__ __align__(16) float s_acc[4][32][FF+4];

    int blk   = blockIdx.x;
    int itile = blk & 15;            // N/32 = 16
    int hh    = (blk >> 4) & 7;
    int b     = blk >> 7;
    int wq    = threadIdx.x >> 5;
    int lane  = threadIdx.x & 31;
    int i     = itile * 32 + lane;
    int ni    = b * NN + i;

    float ar4[FF];
    #pragma unroll
    for (int f = 0; f < FF; f++) ar4[f] = 0.4f * a[f];

    float gri[FF];
    {
        const float4* gp = (const float4*)(d_gr + (ni*HH + hh)*FF);
        #pragma unroll
        for (int q = 0; q < 4; q++) {
            float4 v = gp[q];
            gri[4*q+0] = v.x; gri[4*q+1] = v.y; gri[4*q+2] = v.z; gri[4*q+3] = v.w;
        }
    }
    float base_i = d_dr[ni*HH + hh];   // already 0.6-scaled

    const float*    glbase = d_gl + (b*NN*HH + hh)*FF;
    const float*    grbase = d_gr + (b*NN*HH + hh)*FF;
    const unsigned* abr    = d_adjbits + ni*(NN/32);

    float m = -CUDART_INF_F;
    float l = 0.f;
    float acc[FF];
    #pragma unroll
    for (int f = 0; f < FF; f++) acc[f] = 0.f;

    for (int t = 0; t < (NN/4)/TJ; t++) {          // 8 tiles per warp
        int j0 = wq * (NN/4) + t * TJ;
        __syncwarp();
        #pragma unroll
        for (int r = 0; r < 2; r++) {
            int idx = lane + r*32;                 // 0..63
            int j = idx >> 2, v = idx & 3;
            *(float4*)&s_gl[wq][j][v*4] = *((const float4*)(glbase + (j0+j)*(HH*FF)) + v);
            *(float4*)&s_gr[wq][j][v*4] = *((const float4*)(grbase + (j0+j)*(HH*FF)) + v);
        }
        if (lane < TJ) s_dl[wq][lane] = d_dl[(b*NN + j0 + lane)*HH + hh];
        __syncwarp();

        unsigned mbits = abr[j0 >> 5] >> (j0 & 31);
        float e[TJ];
        float tmax = -CUDART_INF_F;
        #pragma unroll
        for (int j = 0; j < TJ; j++) {
            float a0 = 0.f, a1 = 0.f, a2 = 0.f, a3 = 0.f;
            #pragma unroll
            for (int q = 0; q < 4; q++) {
                float4 g4 = *(const float4*)&s_gl[wq][j][4*q];
                float t0 = gri[4*q+0] + g4.x;
                float t1 = gri[4*q+1] + g4.y;
                float t2 = gri[4*q+2] + g4.z;
                float t3 = gri[4*q+3] + g4.w;
                a0 = fmaf(ar4[4*q+0], fabsf(t0), a0);
                a1 = fmaf(ar4[4*q+1], fabsf(t1), a1);
                a2 = fmaf(ar4[4*q+2], fabsf(t2), a2);
                a3 = fmaf(ar4[4*q+3], fabsf(t3), a3);
            }
            float ej = base_i + s_dl[wq][j] + ((a0+a1) + (a2+a3));
            ej = ((mbits >> j) & 1u) ? ej : -CUDART_INF_F;
            e[j] = ej;
            tmax = fmaxf(tmax, ej);
        }
        if (tmax != -CUDART_INF_F) {               // skip fully-masked tiles (NaN guard)
            float mnew = fmaxf(m, tmax);
            float sc = __expf(m - mnew);           // m=-inf -> 0, acc already 0
            m = mnew;
            l *= sc;
            #pragma unroll
            for (int f = 0; f < FF; f++) acc[f] *= sc;
            #pragma unroll
            for (int j = 0; j < TJ; j++) {
                float p = __expf(e[j] - m);        // masked: exp(-inf)=0
                l += p;
                #pragma unroll
                for (int q = 0; q < 4; q++) {
                    float4 g4 = *(const float4*)&s_gr[wq][j][4*q];
                    acc[4*q+0] = fmaf(p, g4.x, acc[4*q+0]);
                    acc[4*q+1] = fmaf(p, g4.y, acc[4*q+1]);
                    acc[4*q+2] = fmaf(p, g4.z, acc[4*q+2]);
                    acc[4*q+3] = fmaf(p, g4.w, acc[4*q+3]);
                }
            }
        }
    }

    // merge the 4 warps' partial softmax states
    s_m[wq][lane] = m;
    s_l[wq][lane] = l;
    #pragma unroll
    for (int f = 0; f < FF; f++) s_acc[wq][lane][f] = acc[f];
    __syncthreads();

    if (wq == 0) {
        float M = fmaxf(fmaxf(s_m[0][lane], s_m[1][lane]),
                        fmaxf(s_m[2][lane], s_m[3][lane]));   // finite: self-loop guaranteed
        float L = 0.f;
        float o[FF];
        #pragma unroll
        for (int f = 0; f < FF; f++) o[f] = 0.f;
        #pragma unroll
        for (int w = 0; w < 4; w++) {
            float sc = __expf(s_m[w][lane] - M);
            L = fmaf(s_l[w][lane], sc, L);
            #pragma unroll
            for (int f = 0; f < FF; f++)
                o[f] = fmaf(s_acc[w][lane][f], sc, o[f]);
        }
        float inv = 1.f / L;
        float* ho = d_h[src ^ 1] + (ni*HH + hh)*FF;
        #pragma unroll
        for (int q = 0; q < 4; q++) {
            float4 v = make_float4(o[4*q]*inv, o[4*q+1]*inv, o[4*q+2]*inv, o[4*q+3]*inv);
            *(float4*)(ho + 4*q) = v;
        }
    }
}

// ---- out = h @ W_out  ([128]->[1] per node), warp per node ----
__global__ void out_proj_kernel(const float* __restrict__ Wout, float* __restrict__ out)
{
    int gw   = (blockIdx.x * blockDim.x + threadIdx.x) >> 5;
    int lane = threadIdx.x & 31;
    if (gw >= BB*NN) return;
    const float* hp = d_h[1] + gw*DH;   // 3 layers: final state is buffer 1
    float s = 0.f;
    #pragma unroll
    for (int q = 0; q < 4; q++)
        s = fmaf(hp[lane + q*32], Wout[lane + q*32], s);
    #pragma unroll
    for (int off = 16; off; off >>= 1)
        s += __shfl_down_sync(0xffffffffu, s, off);
    if (lane == 0) out[gw] = s;
}

extern "C" void kernel_launch(void* const* d_in, const int* in_sizes, int n_in,
                              void* d_out, int out_size)
{
    const float* nf   = (const float*)d_in[0];
    const int*   adj  = (const int*)  d_in[1];
    const float* Win  = (const float*)d_in[2];
    const float* Wl   = (const float*)d_in[3];
    const float* Wr   = (const float*)d_in[4];
    const float* aa   = (const float*)d_in[5];
    const float* Wout = (const float*)d_in[6];
    float* out = (float*)d_out;
    (void)in_sizes; (void)n_in; (void)out_size;

    pack_adj_kernel<<<256, 256>>>(adj);
    in_proj_kernel<<<(BB*NN*DH)/256, 256>>>(nf, Win);
    for (int L = 0; L < 3; L++) {
        int src = L & 1;
        proj_kernel<<<(BB*NN)/TM, 256>>>(Wl + L*DH*DH, Wr + L*DH*DH, aa + L*FF, src);
        attn_kernel<<<BB*HH*(NN/32), 128>>>(aa + L*FF, src);
    }
    out_proj_kernel<<<256, 256>>>(Wout, out);
}

// round 2
// speedup vs baseline: 1.0188x; 1.0188x over previous
#include <cuda_runtime.h>
#include <math_constants.h>

#define BB 4
#define NN 512
#define HH 8
#define FF 16
#define DH 128
#define TJ 16
#define TM 16

typedef unsigned long long u64;
#define ABSMASK2 0x7FFFFFFF7FFFFFFFull

__device__ __forceinline__ u64 addx2(u64 a, u64 b){ u64 d; asm("add.rn.f32x2 %0,%1,%2;" : "=l"(d) : "l"(a), "l"(b)); return d; }
__device__ __forceinline__ u64 mulx2(u64 a, u64 b){ u64 d; asm("mul.rn.f32x2 %0,%1,%2;" : "=l"(d) : "l"(a), "l"(b)); return d; }
__device__ __forceinline__ u64 fmax2(u64 a, u64 b, u64 c){ u64 d; asm("fma.rn.f32x2 %0,%1,%2,%3;" : "=l"(d) : "l"(a), "l"(b), "l"(c)); return d; }
__device__ __forceinline__ u64 pk2(float x, float y){ u64 r; asm("mov.b64 %0, {%1,%2};" : "=l"(r) : "r"(__float_as_uint(x)), "r"(__float_as_uint(y))); return r; }
__device__ __forceinline__ float2 unpk2(u64 v){ unsigned lo, hi; asm("mov.b64 {%0,%1}, %2;" : "=r"(lo), "=r"(hi) : "l"(v)); return make_float2(__uint_as_float(lo), __uint_as_float(hi)); }

// ---- scratch ----
__device__ float    d_h[2][BB*NN*DH];
__device__ float    d_gl[BB*NN*DH];
__device__ float    d_gr[BB*NN*DH];
__device__ float    d_dl[BB*NN*HH];          // 0.6 * (a . g_l[n,h,:])
__device__ unsigned d_adjbits[BB*NN*(NN/32)];

// ---- fused: h0 = X @ W_in  AND  adj bit-packing ----
__global__ void prep_kernel(const float* __restrict__ x, const float* __restrict__ Win,
                            const int* __restrict__ adj)
{
    if (blockIdx.x < 1024) {
        int idx = blockIdx.x * 256 + threadIdx.x;   // B*N*128
        int n = idx >> 7, d = idx & 127;
        d_h[0][idx] = fmaf(x[n*2], Win[d], x[n*2+1] * Win[DH + d]);
    } else {
        int gw   = ((blockIdx.x - 1024) * 256 + threadIdx.x) >> 5;  // row b*N+i
        int lane = threadIdx.x & 31;
        const int* row = adj + gw * NN;
        #pragma unroll
        for (int w = 0; w < NN/32; w++) {
            unsigned bits = __ballot_sync(0xffffffffu, row[w*32 + lane] != 0);
            if (lane == 0) d_adjbits[gw*(NN/32) + w] = bits;
        }
    }
}

// ---- projections with k-split: g_l = h@Wl, g_r = h@Wr, dl = 0.6*(a.g_l) ----
// 512 threads: d = t&127, sel = (t>>7)&1 (Wl/Wr), kh = t>>8 (k half)
__global__ void __launch_bounds__(512) proj_kernel(const float* __restrict__ Wl,
                                                   const float* __restrict__ Wr,
                                                   const float* __restrict__ a, int src)
{
    __shared__ __align__(16) float sh[TM][DH];
    __shared__ float s_part[2][TM][DH];
    const float* h = d_h[src];
    int n0 = blockIdx.x * TM;
    int t  = threadIdx.x;
    for (int idx = t; idx < TM*DH; idx += 512)
        sh[idx >> 7][idx & 127] = h[n0*DH + idx];
    __syncthreads();

    int d   = t & 127;
    int sel = (t >> 7) & 1;
    int kh  = t >> 8;
    const float* W = sel ? Wr : Wl;

    float acc[TM];
    #pragma unroll
    for (int m = 0; m < TM; m++) acc[m] = 0.f;

    int k0 = kh * 64;
    #pragma unroll 4
    for (int k = k0; k < k0 + 64; k += 4) {
        float w0 = W[(k+0)*DH + d];
        float w1 = W[(k+1)*DH + d];
        float w2 = W[(k+2)*DH + d];
        float w3 = W[(k+3)*DH + d];
        #pragma unroll
        for (int m = 0; m < TM; m++) {
            float4 hv = *(const float4*)&sh[m][k];
            acc[m] = fmaf(hv.x, w0, acc[m]);
            acc[m] = fmaf(hv.y, w1, acc[m]);
            acc[m] = fmaf(hv.z, w2, acc[m]);
            acc[m] = fmaf(hv.w, w3, acc[m]);
        }
    }

    if (kh == 1) {
        #pragma unroll
        for (int m = 0; m < TM; m++) s_part[sel][m][d] = acc[m];
    }
    __syncthreads();
    if (kh == 0) {
        float* g  = sel ? d_gr : d_gl;
        float av  = 0.6f * a[d & 15];
        #pragma unroll
        for (int m = 0; m < TM; m++) {
            float v = acc[m] + s_part[sel][m][d];
            g[(n0+m)*DH + d] = v;
            if (sel == 0) {
                float p = av * v;
                p += __shfl_down_sync(0xffffffffu, p, 8, 16);
                p += __shfl_down_sync(0xffffffffu, p, 4, 16);
                p += __shfl_down_sync(0xffffffffu, p, 2, 16);
                p += __shfl_down_sync(0xffffffffu, p, 1, 16);
                if ((d & 15) == 0) d_dl[(n0+m)*HH + (d >> 4)] = p;
            }
        }
    }
}

// ---- fused GATv2 attention layer (f32x2 packed) ----
// lrelu(t) = 0.6 t + 0.4|t|; softmax shift-invariance lets us drop the per-i
// constant 0.6*(a.gr_i): e'_j = 0.6*(a.gl_j) + sum_f (0.4 a_f)|gr_i + gl_j|_f
__global__ void __launch_bounds__(128, 5) attn_kernel(const float* __restrict__ a, int src)
{
    __shared__ __align__(16) u64 s_gl2[4][TJ][FF/2];
    __shared__ __align__(16) u64 s_gr2[4][TJ][FF/2];
    __shared__ float s_dl[4][TJ];
    __shared__ float s_m[4][32];
    __shared__ float s_l[4][32];
    __shared__ __align__(16) u64 s_acc[4][32][FF/2 + 1];

    int blk   = blockIdx.x;
    int itile = blk & 15;
    int hh    = (blk >> 4) & 7;
    int b     = blk >> 7;
    int wq    = threadIdx.x >> 5;
    int lane  = threadIdx.x & 31;
    int i     = itile * 32 + lane;
    int ni    = b * NN + i;

    u64 ar2[FF/2];
    #pragma unroll
    for (int q = 0; q < FF/2; q++) ar2[q] = pk2(0.4f * a[2*q], 0.4f * a[2*q+1]);

    u64 gri2[FF/2];
    {
        const ulonglong2* gp = (const ulonglong2*)(d_gr + (ni*HH + hh)*FF);
        #pragma unroll
        for (int q = 0; q < 4; q++) {
            ulonglong2 v = gp[q];
            gri2[2*q] = v.x; gri2[2*q+1] = v.y;
        }
    }

    const float*    glbase = d_gl + (b*NN*HH + hh)*FF;
    const float*    grbase = d_gr + (b*NN*HH + hh)*FF;
    const unsigned* abr    = d_adjbits + ni*(NN/32);

    float m = -CUDART_INF_F;
    float l = 0.f;
    u64 acc2[FF/2];
    #pragma unroll
    for (int q = 0; q < FF/2; q++) acc2[q] = 0ull;

    for (int t = 0; t < (NN/4)/TJ; t++) {
        int j0 = wq * (NN/4) + t * TJ;
        __syncwarp();
        #pragma unroll
        for (int r = 0; r < 2; r++) {
            int idx = lane + r*32;
            int j = idx >> 2, v = idx & 3;
            *(float4*)&s_gl2[wq][j][v*2] = *((const float4*)(glbase + (j0+j)*(HH*FF)) + v);
            *(float4*)&s_gr2[wq][j][v*2] = *((const float4*)(grbase + (j0+j)*(HH*FF)) + v);
        }
        if (lane < TJ) s_dl[wq][lane] = d_dl[(b*NN + j0 + lane)*HH + hh];
        __syncwarp();

        unsigned mbits = abr[j0 >> 5] >> (j0 & 31);
        float e[TJ];
        float tmax = -CUDART_INF_F;
        #pragma unroll
        for (int j = 0; j < TJ; j++) {
            const ulonglong2* g2 = (const ulonglong2*)s_gl2[wq][j];
            u64 s0 = 0ull, s1 = 0ull;
            #pragma unroll
            for (int q = 0; q < 4; q++) {
                ulonglong2 gv = g2[q];
                u64 t0 = addx2(gri2[2*q],   gv.x) & ABSMASK2;
                u64 t1 = addx2(gri2[2*q+1], gv.y) & ABSMASK2;
                s0 = fmax2(ar2[2*q],   t0, s0);
                s1 = fmax2(ar2[2*q+1], t1, s1);
            }
            float2 sv = unpk2(addx2(s0, s1));
            float ej = (sv.x + sv.y) + s_dl[wq][j];
            ej = ((mbits >> j) & 1u) ? ej : -CUDART_INF_F;
            e[j] = ej;
            tmax = fmaxf(tmax, ej);
        }
        if (tmax != -CUDART_INF_F) {
            float mnew = fmaxf(m, tmax);
            float sc = __expf(m - mnew);
            m = mnew;
            l *= sc;
            u64 sc2 = pk2(sc, sc);
            #pragma unroll
            for (int q = 0; q < FF/2; q++) acc2[q] = mulx2(acc2[q], sc2);
            #pragma unroll
            for (int j = 0; j < TJ; j++) {
                float p = __expf(e[j] - m);
                l += p;
                u64 p2 = pk2(p, p);
                const ulonglong2* g2 = (const ulonglong2*)s_gr2[wq][j];
                #pragma unroll
                for (int q = 0; q < 4; q++) {
                    ulonglong2 gv = g2[q];
                    acc2[2*q]   = fmax2(p2, gv.x, acc2[2*q]);
                    acc2[2*q+1] = fmax2(p2, gv.y, acc2[2*q+1]);
                }
            }
        }
    }

    // merge the 4 warps' partial softmax states
    s_m[wq][lane] = m;
    s_l[wq][lane] = l;
    #pragma unroll
    for (int q = 0; q < FF/2; q++) s_acc[wq][lane][q] = acc2[q];
    __syncthreads();

    if (wq == 0) {
        float M = fmaxf(fmaxf(s_m[0][lane], s_m[1][lane]),
                        fmaxf(s_m[2][lane], s_m[3][lane]));
        float L = 0.f;
        u64 o2[FF/2];
        #pragma unroll
        for (int q = 0; q < FF/2; q++) o2[q] = 0ull;
        #pragma unroll
        for (int w = 0; w < 4; w++) {
            float sc = __expf(s_m[w][lane] - M);
            L = fmaf(s_l[w][lane], sc, L);
            u64 sc2 = pk2(sc, sc);
            #pragma unroll
            for (int q = 0; q < FF/2; q++)
                o2[q] = fmax2(sc2, s_acc[w][lane][q], o2[q]);
        }
        float inv = 1.f / L;
        u64 inv2 = pk2(inv, inv);
        u64* ho = (u64*)(d_h[src ^ 1] + (ni*HH + hh)*FF);
        #pragma unroll
        for (int q = 0; q < FF/2; q++) ho[q] = mulx2(o2[q], inv2);
    }
}

// ---- out = h @ W_out, warp per node ----
__global__ void out_proj_kernel(const float* __restrict__ Wout, float* __restrict__ out)
{
    int gw   = (blockIdx.x * blockDim.x + threadIdx.x) >> 5;
    int lane = threadIdx.x & 31;
    if (gw >= BB*NN) return;
    const float* hp = d_h[1] + gw*DH;
    float s = 0.f;
    #pragma unroll
    for (int q = 0; q < 4; q++)
        s = fmaf(hp[lane + q*32], Wout[lane + q*32], s);
    #pragma unroll
    for (int off = 16; off; off >>= 1)
        s += __shfl_down_sync(0xffffffffu, s, off);
    if (lane == 0) out[gw] = s;
}

extern "C" void kernel_launch(void* const* d_in, const int* in_sizes, int n_in,
                              void* d_out, int out_size)
{
    const float* nf   = (const float*)d_in[0];
    const int*   adj  = (const int*)  d_in[1];
    const float* Win  = (const float*)d_in[2];
    const float* Wl   = (const float*)d_in[3];
    const float* Wr   = (const float*)d_in[4];
    const float* aa   = (const float*)d_in[5];
    const float* Wout = (const float*)d_in[6];
    float* out = (float*)d_out;
    (void)in_sizes; (void)n_in; (void)out_size;

    prep_kernel<<<1024 + 256, 256>>>(nf, Win, adj);
    for (int L = 0; L < 3; L++) {
        int src = L & 1;
        proj_kernel<<<(BB*NN)/TM, 512>>>(Wl + L*DH*DH, Wr + L*DH*DH, aa + L*FF, src);
        attn_kernel<<<BB*HH*(NN/32), 128>>>(aa + L*FF, src);
    }
    out_proj_kernel<<<256, 256>>>(Wout, out);
}